// round 16
// baseline (speedup 1.0000x reference)
#include <cuda_runtime.h>
#include <cuda_bf16.h>
#include <math.h>
#include <stdint.h>

#define Bz 4
#define NN 2048
#define DD 512
#define HH 8
#define HD 64
#define MT (Bz*NN)
#define BH (Bz*HH)

// ---------------- scratch (device globals) ----------------
__device__ float g_qkv[MT * 3 * DD];
__device__ float g_msg[MT * DD];
__device__ float g_hin[MT * 2*DD];
__device__ float g_h1 [MT * 2*DD];
__device__ float g_wt [1536 * 1024];      // weight transpose scratch (fp32)

__device__ __nv_bfloat16 g_qh[BH * NN * HD];
__device__ __nv_bfloat16 g_kh[BH * NN * HD];
__device__ __nv_bfloat16 g_vt[BH * HD * NN];

// int8 two-digit activation buffers + row scales
__device__ char  g_aq1[MT * 1024];
__device__ char  g_aq2[MT * 1024];
__device__ float g_sa [MT];
// weights (transposed [N][K]) int8 digits + per-N scales
__device__ char  g_wq1[1536 * 512],  g_wq2[1536 * 512];   __device__ float g_swq[1536];
__device__ char  g_wo1[512 * 512],   g_wo2[512 * 512];    __device__ float g_swo[512];
__device__ char  g_w11[1024 * 1024], g_w12[1024 * 1024];  __device__ float g_sw1[1024];
__device__ char  g_w21[512 * 1024],  g_w22[512 * 1024];   __device__ float g_sw2[512];

// ================= helpers =================
static __device__ __forceinline__ uint32_t su32(const void* p) {
    uint32_t a;
    asm("{ .reg .u64 t; cvta.to.shared.u64 t, %1; cvt.u32.u64 %0, t; }"
        : "=r"(a) : "l"(p));
    return a;
}
static __device__ __forceinline__ void ldm_x4(uint32_t* r, uint32_t addr) {
    asm volatile("ldmatrix.sync.aligned.m8n8.x4.shared.b16 {%0,%1,%2,%3}, [%4];"
                 : "=r"(r[0]), "=r"(r[1]), "=r"(r[2]), "=r"(r[3]) : "r"(addr));
}
static __device__ __forceinline__ void ldm_x2(uint32_t* r, uint32_t addr) {
    asm volatile("ldmatrix.sync.aligned.m8n8.x2.shared.b16 {%0,%1}, [%2];"
                 : "=r"(r[0]), "=r"(r[1]) : "r"(addr));
}
static __device__ __forceinline__ void mma16816(float* c, const uint32_t* a,
                                                const uint32_t* b) {
    asm volatile(
        "mma.sync.aligned.m16n8k16.row.col.f32.bf16.bf16.f32 "
        "{%0,%1,%2,%3}, {%4,%5,%6,%7}, {%8,%9}, {%0,%1,%2,%3};"
        : "+f"(c[0]), "+f"(c[1]), "+f"(c[2]), "+f"(c[3])
        : "r"(a[0]), "r"(a[1]), "r"(a[2]), "r"(a[3]), "r"(b[0]), "r"(b[1]));
}
static __device__ __forceinline__ void imma(int* c, const uint32_t* a,
                                            const uint32_t* b) {
    asm volatile(
        "mma.sync.aligned.m16n8k32.row.col.s32.s8.s8.s32 "
        "{%0,%1,%2,%3}, {%4,%5,%6,%7}, {%8,%9}, {%0,%1,%2,%3};"
        : "+r"(c[0]), "+r"(c[1]), "+r"(c[2]), "+r"(c[3])
        : "r"(a[0]), "r"(a[1]), "r"(a[2]), "r"(a[3]), "r"(b[0]), "r"(b[1]));
}
static __device__ __forceinline__ uint32_t pack_bf16x2(float lo, float hi) {
    uint32_t d;
    asm("cvt.rn.bf16x2.f32 %0, %1, %2;" : "=r"(d) : "f"(hi), "f"(lo));
    return d;
}
static __device__ __forceinline__ void cp16(uint32_t dst, const void* src) {
    asm volatile("cp.async.cg.shared.global [%0], [%1], 16;"
                 :: "r"(dst), "l"(src));
}
#define CP_COMMIT() asm volatile("cp.async.commit_group;" ::: "memory")
#define CP_WAIT0()  asm volatile("cp.async.wait_group 0;" ::: "memory")
#define CP_WAIT1()  asm volatile("cp.async.wait_group 1;" ::: "memory")

// ================= row quantization: fp32 [R x K] -> 2-digit int8 ==========
__global__ __launch_bounds__(256) void rowquant(
    const float* __restrict__ A, char* __restrict__ d1, char* __restrict__ d2,
    float* __restrict__ s, int K)
{
    const int w = threadIdx.x >> 5, lane = threadIdx.x & 31;
    const int row = blockIdx.x * 8 + w;
    const float4* src = (const float4*)(A + (size_t)row * K);
    const int nf4 = K >> 7;               // float4 per lane (4 or 8)

    float mx = 0.f;
    for (int i = 0; i < nf4; i++) {
        float4 v = src[lane + i * 32];
        mx = fmaxf(mx, fmaxf(fmaxf(fabsf(v.x), fabsf(v.y)),
                             fmaxf(fabsf(v.z), fabsf(v.w))));
    }
#pragma unroll
    for (int off = 16; off >= 1; off >>= 1)
        mx = fmaxf(mx, __shfl_xor_sync(0xffffffffu, mx, off));
    float inv = mx > 0.f ? 127.f / mx : 0.f;
    if (lane == 0) s[row] = mx * (1.f / 127.f);

    char4* p1 = (char4*)(d1 + (size_t)row * K);
    char4* p2 = (char4*)(d2 + (size_t)row * K);
    for (int i = 0; i < nf4; i++) {
        float4 v = src[lane + i * 32];
        float a0 = v.x * inv, a1 = v.y * inv, a2 = v.z * inv, a3 = v.w * inv;
        float q0 = rintf(a0), q1 = rintf(a1), q2 = rintf(a2), q3 = rintf(a3);
        char4 c1 = make_char4((char)(int)q0, (char)(int)q1,
                              (char)(int)q2, (char)(int)q3);
        char4 c2 = make_char4((char)(int)rintf((a0 - q0) * 254.f),
                              (char)(int)rintf((a1 - q1) * 254.f),
                              (char)(int)rintf((a2 - q2) * 254.f),
                              (char)(int)rintf((a3 - q3) * 254.f));
        p1[lane + i * 32] = c1;
        p2[lane + i * 32] = c2;
    }
}

// w[K][N] fp32 -> wt[N][K] fp32
__global__ void wtrans(const float* __restrict__ w, float* __restrict__ wt,
                       int K, int N)
{
    __shared__ float t[32][33];
    int n0 = blockIdx.x * 32, k0 = blockIdx.y * 32;
    int tx = threadIdx.x, ty = threadIdx.y;
#pragma unroll
    for (int i = 0; i < 4; i++)
        t[ty + i * 8][tx] = w[(size_t)(k0 + ty + i * 8) * N + n0 + tx];
    __syncthreads();
#pragma unroll
    for (int i = 0; i < 4; i++)
        wt[(size_t)(n0 + ty + i * 8) * K + k0 + tx] = t[tx][ty + i * 8];
}

// ================= int8 two-digit GEMM via mma.sync s8 ====================
// C = sA[row]*sB[col]*(P + Q/254) + bias (+resid). Tiles 128x128x64.
// smem row = 64 int8 + pad -> 80B stride (conflict-free, 16B aligned).
#define SRB 80
#define IST (128 * SRB)                  // bytes per sub-buffer
__global__ __launch_bounds__(256, 1)
void gemm_i8(const char* __restrict__ A1, const char* __restrict__ A2,
             const float* __restrict__ sA,
             const char* __restrict__ B1, const char* __restrict__ B2,
             const float* __restrict__ sB,
             const float* __restrict__ bias, const float* __restrict__ resid,
             float* __restrict__ C, int M, int N, int K, int ldc, int coff)
{
    extern __shared__ char dyn8[];
    const int tid = threadIdx.x;
    const int wid = tid >> 5, lane = tid & 31;
    const int wm = wid >> 2, wn = wid & 3;
    const int m0 = blockIdx.y * 128, n0 = blockIdx.x * 128;
    const uint32_t sb = su32(dyn8);

    int accP[4][4][4], accQ[4][4][4];
#pragma unroll
    for (int i = 0; i < 4; i++)
#pragma unroll
        for (int j = 0; j < 4; j++)
#pragma unroll
            for (int e = 0; e < 4; e++) { accP[i][j][e] = 0; accQ[i][j][e] = 0; }

    uint32_t pA[4], pB[4];
    {
        int rA8 = ((lane >> 3) & 1) * 8 + (lane & 7);
        int cA  = (lane >> 4);
#pragma unroll
        for (int mi = 0; mi < 4; mi++)
            pA[mi] = (uint32_t)((wm * 64 + mi * 16 + rA8) * SRB + cA * 16);
        int rB = (lane & 7), cB = (lane >> 3) & 1;
#pragma unroll
        for (int ni = 0; ni < 4; ni++)
            pB[ni] = (uint32_t)((wn * 32 + ni * 8 + rB) * SRB + cB * 16);
    }

    const int r0s = (tid + 0)   >> 2, c80 = ((tid + 0)   & 3) * 16;
    const int r1s = (tid + 256) >> 2, c81 = ((tid + 256) & 3) * 16;

#define GLOAD8(stage, kt_) do {                                               \
    uint32_t base = sb + (uint32_t)(stage) * (4 * IST);                       \
    int ke_ = (kt_);                                                          \
    size_t ga0 = (size_t)(m0 + r0s) * K + ke_ + c80;                          \
    size_t ga1 = (size_t)(m0 + r1s) * K + ke_ + c81;                          \
    size_t gb0 = (size_t)(n0 + r0s) * K + ke_ + c80;                          \
    size_t gb1 = (size_t)(n0 + r1s) * K + ke_ + c81;                          \
    uint32_t s0 = (uint32_t)(r0s * SRB + c80);                                \
    uint32_t s1 = (uint32_t)(r1s * SRB + c81);                                \
    cp16(base + s0,           A1 + ga0);  cp16(base + s1,           A1 + ga1);\
    cp16(base + IST + s0,     A2 + ga0);  cp16(base + IST + s1,     A2 + ga1);\
    cp16(base + 2*IST + s0,   B1 + gb0);  cp16(base + 2*IST + s1,   B1 + gb1);\
    cp16(base + 3*IST + s0,   B2 + gb0);  cp16(base + 3*IST + s1,   B2 + gb1);\
} while (0)

    const int nkt = K >> 6;
    GLOAD8(0, 0); CP_COMMIT();

    for (int kt = 0; kt < nkt; kt++) {
        if (kt + 1 < nkt) { GLOAD8((kt + 1) & 1, (kt + 1) << 6); CP_COMMIT(); CP_WAIT1(); }
        else              { CP_WAIT0(); }
        __syncthreads();

        const uint32_t base = sb + (uint32_t)(kt & 1) * (4 * IST);
        const uint32_t aA1 = base, aA2 = base + IST;
        const uint32_t aB1 = base + 2 * IST, aB2 = base + 3 * IST;

#pragma unroll
        for (int ks = 0; ks < 2; ks++) {
            const uint32_t koff = ks * 32;       // 32 bytes = k32
            uint32_t af[4][4], b1[4][2], b2[4][2];
#pragma unroll
            for (int ni = 0; ni < 4; ni++) {
                ldm_x2(b1[ni], aB1 + pB[ni] + koff);
                ldm_x2(b2[ni], aB2 + pB[ni] + koff);
            }
#pragma unroll
            for (int mi = 0; mi < 4; mi++)
                ldm_x4(af[mi], aA1 + pA[mi] + koff);
#pragma unroll
            for (int mi = 0; mi < 4; mi++)
#pragma unroll
                for (int ni = 0; ni < 4; ni++) {
                    imma(accP[mi][ni], af[mi], b1[ni]);
                    imma(accQ[mi][ni], af[mi], b2[ni]);
                }
#pragma unroll
            for (int mi = 0; mi < 4; mi++)
                ldm_x4(af[mi], aA2 + pA[mi] + koff);
#pragma unroll
            for (int mi = 0; mi < 4; mi++)
#pragma unroll
                for (int ni = 0; ni < 4; ni++)
                    imma(accQ[mi][ni], af[mi], b1[ni]);
        }
        __syncthreads();
    }

    const int gp = lane >> 2, tg = lane & 3;
    float sAr[4][2];
#pragma unroll
    for (int mi = 0; mi < 4; mi++) {
        int r = m0 + wm * 64 + mi * 16 + gp;
        sAr[mi][0] = sA[r];
        sAr[mi][1] = sA[r + 8];
    }
    const float i254 = 1.f / 254.f;
#pragma unroll
    for (int mi = 0; mi < 4; mi++) {
#pragma unroll
        for (int ni = 0; ni < 4; ni++) {
            int col = n0 + wn * 32 + ni * 8 + tg * 2;
            float sb0 = sB[col], sb1 = sB[col + 1];
            float b0 = bias[col], b1v = bias[col + 1];
#pragma unroll
            for (int half = 0; half < 2; half++) {
                int row = m0 + wm * 64 + mi * 16 + gp + half * 8;
                float sa = sAr[mi][half];
                float v0 = sa * sb0 * ((float)accP[mi][ni][half*2+0]
                                        + (float)accQ[mi][ni][half*2+0] * i254) + b0;
                float v1 = sa * sb1 * ((float)accP[mi][ni][half*2+1]
                                        + (float)accQ[mi][ni][half*2+1] * i254) + b1v;
                if (resid) {
                    const float2 rv = *(const float2*)(resid + (size_t)row * N + col);
                    v0 += rv.x; v1 += rv.y;
                }
                *(float2*)(C + (size_t)row * ldc + coff + col) = make_float2(v0, v1);
            }
        }
    }
#undef GLOAD8
}

// ---------------- RoPE -> bf16 q (x0.125), k ----------------
__global__ __launch_bounds__(256) void rope_bf(const float* __restrict__ freqs)
{
    int idx = blockIdx.x * blockDim.x + threadIdx.x;
    if (idx >= Bz * NN * HH * 32) return;
    int i = idx & 31;
    int h = (idx >> 5) & 7;
    int n = (idx >> 8) & (NN - 1);
    int b = idx >> 19;

    float f = freqs[(size_t)(b * NN + n) * 32 + i];
    float c = cosf(f), s = sinf(f);

    size_t rowbase = (size_t)(b * NN + n) * (3 * DD);
    int qcol = h * HD + 2 * i;
    float q1 = g_qkv[rowbase + qcol],      q2 = g_qkv[rowbase + qcol + 1];
    float k1 = g_qkv[rowbase + DD + qcol], k2 = g_qkv[rowbase + DD + qcol + 1];

    size_t o = ((size_t)(b * HH + h) * NN + n) * HD + 2 * i;
    __nv_bfloat162 qq, kk;
    qq.x = __float2bfloat16((q1 * c - q2 * s) * 0.125f);
    qq.y = __float2bfloat16((q1 * s + q2 * c) * 0.125f);
    kk.x = __float2bfloat16(k1 * c - k2 * s);
    kk.y = __float2bfloat16(k1 * s + k2 * c);
    *(__nv_bfloat162*)(g_qh + o) = qq;
    *(__nv_bfloat162*)(g_kh + o) = kk;
}

// ---------------- V transpose ----------------
__global__ void vtrans()
{
    __shared__ float t[32][33];
    int n0 = blockIdx.x * 32;
    int d0 = blockIdx.y * 32;
    int bh = blockIdx.z;
    int b = bh >> 3, h = bh & 7;
    int tx = threadIdx.x, ty = threadIdx.y;
#pragma unroll
    for (int i = 0; i < 4; i++) {
        int n = n0 + ty + i * 8;
        t[ty + i * 8][tx] =
            g_qkv[(size_t)(b * NN + n) * (3 * DD) + 2 * DD + h * HD + d0 + tx];
    }
    __syncthreads();
#pragma unroll
    for (int i = 0; i < 4; i++) {
        int d = d0 + ty + i * 8;
        g_vt[((size_t)bh * HD + d) * NN + n0 + tx] =
            __float2bfloat16(t[tx][ty + i * 8]);
    }
}

// ---------------- attention via mma.sync bf16, cp.async (validated R13/R15) -
#define AR 72
#define ASTG (64 * AR)
__global__ __launch_bounds__(256, 1) void attn_mma()
{
    extern __shared__ __nv_bfloat16 adyn[];
    const int tid = threadIdx.x;
    const int wid = tid >> 5, lane = tid & 31;
    const int gp = lane >> 2, tg = lane & 3;
    const int bh = blockIdx.y;
    const int b = bh >> 3, h = bh & 7;
    const int q0 = blockIdx.x * 128;
    const size_t qbase = (size_t)bh * NN * HD;
    const uint32_t sb = su32(adyn);
    const uint32_t aQ = sb;

#pragma unroll
    for (int u = 0; u < 4; u++) {
        int s = tid + u * 256;
        int r = s >> 3, c8 = (s & 7) * 8;
        cp16(aQ + (uint32_t)(r * AR + c8) * 2,
             g_qh + qbase + (size_t)(q0 + r) * HD + c8);
    }
    CP_COMMIT();

    const int rks0 = (tid + 0)   >> 3, ck0 = ((tid + 0)   & 7) * 8;
    const int rks1 = (tid + 256) >> 3, ck1 = ((tid + 256) & 7) * 8;

#define ALOAD(stage, kt_) do {                                                 \
    uint32_t kb_ = sb + (uint32_t)(128 * AR + (stage) * 2 * ASTG) * 2;         \
    uint32_t vb_ = kb_ + ASTG * 2;                                             \
    int kv0 = (kt_) * 64;                                                      \
    cp16(kb_ + (uint32_t)(rks0 * AR + ck0) * 2,                                \
         g_kh + qbase + (size_t)(kv0 + rks0) * HD + ck0);                      \
    cp16(kb_ + (uint32_t)(rks1 * AR + ck1) * 2,                                \
         g_kh + qbase + (size_t)(kv0 + rks1) * HD + ck1);                      \
    cp16(vb_ + (uint32_t)(rks0 * AR + ck0) * 2,                                \
         g_vt + ((size_t)bh * HD + rks0) * NN + kv0 + ck0);                    \
    cp16(vb_ + (uint32_t)(rks1 * AR + ck1) * 2,                                \
         g_vt + ((size_t)bh * HD + rks1) * NN + kv0 + ck1);                    \
} while (0)

    ALOAD(0, 0); CP_COMMIT();
    CP_WAIT1();
    __syncthreads();

    uint32_t qf[4][4];
    {
        int rA8 = ((lane >> 3) & 1) * 8 + (lane & 7);
        int cA  = (lane >> 4);
        uint32_t base = (uint32_t)((wid * 16 + rA8) * (AR * 2) + cA * 16);
#pragma unroll
        for (int kc = 0; kc < 4; kc++)
            ldm_x4(qf[kc], aQ + base + kc * 32);
    }
    const uint32_t pB = (uint32_t)((lane & 7) * (AR * 2) + ((lane >> 3) & 1) * 16);

    float o[8][4];
    float m0 = -INFINITY, m1 = -INFINITY, l0 = 0.f, l1 = 0.f;
#pragma unroll
    for (int j = 0; j < 8; j++)
#pragma unroll
        for (int e = 0; e < 4; e++) o[j][e] = 0.f;

    const int nkt = NN / 64;
    for (int kt = 0; kt < nkt; kt++) {
        if (kt + 1 < nkt) { ALOAD((kt + 1) & 1, kt + 1); CP_COMMIT(); CP_WAIT1(); }
        else              { CP_WAIT0(); }
        __syncthreads();

        const uint32_t aK = sb + (uint32_t)(128 * AR + (kt & 1) * 2 * ASTG) * 2;
        const uint32_t aV = aK + ASTG * 2;

        float sc[8][4];
#pragma unroll
        for (int j = 0; j < 8; j++)
#pragma unroll
            for (int e = 0; e < 4; e++) sc[j][e] = 0.f;
#pragma unroll
        for (int j = 0; j < 8; j++) {
            uint32_t kb[4][2];
#pragma unroll
            for (int kc = 0; kc < 4; kc++)
                ldm_x2(kb[kc], aK + pB + j * 8 * (AR * 2) + kc * 32);
#pragma unroll
            for (int kc = 0; kc < 4; kc++)
                mma16816(sc[j], qf[kc], kb[kc]);
        }

        float mx0 = -INFINITY, mx1 = -INFINITY;
#pragma unroll
        for (int j = 0; j < 8; j++) {
            mx0 = fmaxf(mx0, fmaxf(sc[j][0], sc[j][1]));
            mx1 = fmaxf(mx1, fmaxf(sc[j][2], sc[j][3]));
        }
#pragma unroll
        for (int off = 1; off <= 2; off <<= 1) {
            mx0 = fmaxf(mx0, __shfl_xor_sync(0xffffffffu, mx0, off));
            mx1 = fmaxf(mx1, __shfl_xor_sync(0xffffffffu, mx1, off));
        }
        float nm0 = fmaxf(m0, mx0), nm1 = fmaxf(m1, mx1);
        float cr0 = __expf(m0 - nm0), cr1 = __expf(m1 - nm1);
        float rs0 = 0.f, rs1 = 0.f;
        uint32_t ph[8][2];
#pragma unroll
        for (int j = 0; j < 8; j++) {
            float p0 = __expf(sc[j][0] - nm0);
            float p1 = __expf(sc[j][1] - nm0);
            float p2 = __expf(sc[j][2] - nm1);
            float p3 = __expf(sc[j][3] - nm1);
            rs0 += p0 + p1; rs1 += p2 + p3;
            ph[j][0] = pack_bf16x2(p0, p1);
            ph[j][1] = pack_bf16x2(p2, p3);
        }
#pragma unroll
        for (int off = 1; off <= 2; off <<= 1) {
            rs0 += __shfl_xor_sync(0xffffffffu, rs0, off);
            rs1 += __shfl_xor_sync(0xffffffffu, rs1, off);
        }
        l0 = l0 * cr0 + rs0;  m0 = nm0;
        l1 = l1 * cr1 + rs1;  m1 = nm1;
#pragma unroll
        for (int j = 0; j < 8; j++) {
            o[j][0] *= cr0; o[j][1] *= cr0;
            o[j][2] *= cr1; o[j][3] *= cr1;
        }

#pragma unroll
        for (int t = 0; t < 4; t++) {
            uint32_t af[4] = { ph[2 * t][0], ph[2 * t][1],
                               ph[2 * t + 1][0], ph[2 * t + 1][1] };
#pragma unroll
            for (int j = 0; j < 8; j++) {
                uint32_t vb[2];
                ldm_x2(vb, aV + pB + j * 8 * (AR * 2) + t * 32);
                mma16816(o[j], af, vb);
            }
        }
        __syncthreads();
    }

    float inv0 = 1.f / l0, inv1 = 1.f / l1;
    int row0 = q0 + wid * 16 + gp;
#pragma unroll
    for (int j = 0; j < 8; j++) {
        int col = h * HD + j * 8 + tg * 2;
        *(float2*)(g_msg + (size_t)(b * NN + row0) * DD + col) =
            make_float2(o[j][0] * inv0, o[j][1] * inv0);
        *(float2*)(g_msg + (size_t)(b * NN + row0 + 8) * DD + col) =
            make_float2(o[j][2] * inv1, o[j][3] * inv1);
    }
#undef ALOAD
}

// ---------------- copy x into first half of concat buffer ----------------
__global__ __launch_bounds__(256) void copy_x(const float* __restrict__ x)
{
    int s = blockIdx.x * blockDim.x + threadIdx.x;
    if (s >= MT * 128) return;
    int row = s >> 7, c4 = s & 127;
    ((float4*)g_hin)[(size_t)row * 256 + c4] = ((const float4*)x)[s];
}

// outproj result goes into g_hin cols 512.. ; msg quant reads g_msg.

// ---------------- LayerNorm(1024) + exact GELU (fp32 in/out) ---------------
__global__ __launch_bounds__(256) void ln_gelu(const float* __restrict__ gam,
                                               const float* __restrict__ bet)
{
    const int row = blockIdx.x;
    const int tid = threadIdx.x;
    float* r = g_h1 + (size_t)row * 1024;
    float4 v = *(const float4*)(r + tid * 4);
    float s  = v.x + v.y + v.z + v.w;
    float sq = v.x*v.x + v.y*v.y + v.z*v.z + v.w*v.w;
#pragma unroll
    for (int off = 16; off >= 1; off >>= 1) {
        s  += __shfl_xor_sync(0xffffffffu, s, off);
        sq += __shfl_xor_sync(0xffffffffu, sq, off);
    }
    __shared__ float rs[8], rq[8];
    if ((tid & 31) == 0) { rs[tid >> 5] = s; rq[tid >> 5] = sq; }
    __syncthreads();
    if (tid == 0) {
        float a = 0.f, bq = 0.f;
#pragma unroll
        for (int w = 0; w < 8; w++) { a += rs[w]; bq += rq[w]; }
        rs[0] = a; rq[0] = bq;
    }
    __syncthreads();
    float mu = rs[0] * (1.f / 1024.f);
    float var = rq[0] * (1.f / 1024.f) - mu * mu;
    float rstd = rsqrtf(var + 1e-5f);
    int c = tid * 4;
    float y[4] = { v.x, v.y, v.z, v.w };
    float4 ov;
    float* po = (float*)&ov;
#pragma unroll
    for (int e = 0; e < 4; e++) {
        float t = (y[e] - mu) * rstd * gam[c + e] + bet[c + e];
        po[e] = 0.5f * t * (1.f + erff(t * 0.70710678118654752440f));
    }
    *(float4*)(r + c) = ov;
}

// ---------------- host orchestration ----------------
extern "C" void kernel_launch(void* const* d_in, const int* in_sizes, int n_in,
                              void* d_out, int out_size)
{
    const float* x      = (const float*)d_in[0];
    const float* freqs  = (const float*)d_in[1];
    const float* wqkv_w = (const float*)d_in[2];
    const float* wqkv_b = (const float*)d_in[3];
    const float* out_w  = (const float*)d_in[4];
    const float* out_b  = (const float*)d_in[5];
    const float* ffn1_w = (const float*)d_in[6];
    const float* ffn1_b = (const float*)d_in[7];
    const float* ln_g   = (const float*)d_in[8];
    const float* ln_b   = (const float*)d_in[9];
    const float* ffn2_w = (const float*)d_in[10];
    const float* ffn2_b = (const float*)d_in[11];
    float* out = (float*)d_out;

    float *p_qkv, *p_msg, *p_hin, *p_h1, *p_wt, *p_sa;
    cudaGetSymbolAddress((void**)&p_qkv, g_qkv);
    cudaGetSymbolAddress((void**)&p_msg, g_msg);
    cudaGetSymbolAddress((void**)&p_hin, g_hin);
    cudaGetSymbolAddress((void**)&p_h1,  g_h1);
    cudaGetSymbolAddress((void**)&p_wt,  g_wt);
    cudaGetSymbolAddress((void**)&p_sa,  g_sa);
    char *aq1, *aq2;
    cudaGetSymbolAddress((void**)&aq1, g_aq1);
    cudaGetSymbolAddress((void**)&aq2, g_aq2);
    char *wq1, *wq2, *wo1, *wo2, *w11, *w12, *w21, *w22;
    float *swq, *swo, *sw1, *sw2;
    cudaGetSymbolAddress((void**)&wq1, g_wq1); cudaGetSymbolAddress((void**)&wq2, g_wq2);
    cudaGetSymbolAddress((void**)&wo1, g_wo1); cudaGetSymbolAddress((void**)&wo2, g_wo2);
    cudaGetSymbolAddress((void**)&w11, g_w11); cudaGetSymbolAddress((void**)&w12, g_w12);
    cudaGetSymbolAddress((void**)&w21, g_w21); cudaGetSymbolAddress((void**)&w22, g_w22);
    cudaGetSymbolAddress((void**)&swq, g_swq); cudaGetSymbolAddress((void**)&swo, g_swo);
    cudaGetSymbolAddress((void**)&sw1, g_sw1); cudaGetSymbolAddress((void**)&sw2, g_sw2);

    const int gsm = 4 * IST * 2;                         // 81920
    cudaFuncSetAttribute(gemm_i8, cudaFuncAttributeMaxDynamicSharedMemorySize, gsm);
    const int asm_ = (128 * AR + 4 * ASTG) * (int)sizeof(__nv_bfloat16);
    cudaFuncSetAttribute(attn_mma, cudaFuncAttributeMaxDynamicSharedMemorySize, asm_);

    dim3 wblk(32, 8);

    // ---- weights: transpose + 2-digit quantize ----
    wtrans<<<dim3(1536/32, 512/32),  wblk>>>(wqkv_w, p_wt, 512, 1536);
    rowquant<<<1536/8, 256>>>(p_wt, wq1, wq2, swq, 512);
    wtrans<<<dim3(512/32, 512/32),   wblk>>>(out_w,  p_wt, 512, 512);
    rowquant<<<512/8, 256>>>(p_wt, wo1, wo2, swo, 512);
    wtrans<<<dim3(1024/32, 1024/32), wblk>>>(ffn1_w, p_wt, 1024, 1024);
    rowquant<<<1024/8, 256>>>(p_wt, w11, w12, sw1, 1024);
    wtrans<<<dim3(512/32, 1024/32),  wblk>>>(ffn2_w, p_wt, 1024, 512);
    rowquant<<<512/8, 256>>>(p_wt, w21, w22, sw2, 1024);

    // 1) qkv = x @ wqkv + b
    rowquant<<<MT/8, 256>>>(x, aq1, aq2, p_sa, 512);
    gemm_i8<<<dim3(1536/128, MT/128), 256, gsm>>>(
        aq1, aq2, p_sa, wq1, wq2, swq, wqkv_b, nullptr, p_qkv,
        MT, 1536, 512, 1536, 0);

    // 2) RoPE, V transpose, x -> concat buffer
    rope_bf<<<(Bz * NN * HH * 32 + 255) / 256, 256>>>(freqs);
    vtrans<<<dim3(NN/32, HD/32, BH), wblk>>>();
    copy_x<<<(MT * 128 + 255) / 256, 256>>>(x);

    // 3) attention -> g_msg
    attn_mma<<<dim3(NN/128, BH), 256, asm_>>>();

    // 4) out proj -> g_hin cols 512..
    rowquant<<<MT/8, 256>>>(p_msg, aq1, aq2, p_sa, 512);
    gemm_i8<<<dim3(512/128, MT/128), 256, gsm>>>(
        aq1, aq2, p_sa, wo1, wo2, swo, out_b, nullptr, p_hin,
        MT, 512, 512, 1024, 512);

    // 5) ffn1
    rowquant<<<MT/8, 256>>>(p_hin, aq1, aq2, p_sa, 1024);
    gemm_i8<<<dim3(1024/128, MT/128), 256, gsm>>>(
        aq1, aq2, p_sa, w11, w12, sw1, ffn1_b, nullptr, p_h1,
        MT, 1024, 1024, 1024, 0);

    // 6) LN + GELU
    ln_gelu<<<MT, 256>>>(ln_g, ln_b);

    // 7) ffn2 + residual
    rowquant<<<MT/8, 256>>>(p_h1, aq1, aq2, p_sa, 1024);
    gemm_i8<<<dim3(512/128, MT/128), 256, gsm>>>(
        aq1, aq2, p_sa, w21, w22, sw2, ffn2_b, x, out,
        MT, 512, 1024, 512, 0);
}